// round 5
// baseline (speedup 1.0000x reference)
#include <cuda_runtime.h>

#define NMAX 100000
#define EMAX 1600000
#define NGRAPH 256

// ---------------- static scratch (no allocation allowed) ----------------
__device__ float g_deg[NMAX];
__device__ float g_dinv[NMAX];
__device__ float g_dinv2[NMAX];
__device__ int   g_src[EMAX];
__device__ int   g_dst[EMAX];
__device__ int   g_b32[NMAX];
__device__ float g_norm[EMAX];
__device__ float g_h1[(size_t)NMAX * 128];
__device__ float g_t [(size_t)NMAX * 64];
__device__ float g_y [(size_t)NMAX * 64];
__device__ float g_pool[NGRAPH * 32];
__device__ float g_cnt[NGRAPH];
__device__ int   g_flag_ei;   // 1 = int64 data, 0 = int32 data
__device__ int   g_flag_b;

// ---------------- dtype detection (device-side, graph-safe) -------------
// Scan [start, start+count) of p interpreted as int64; if any value falls
// outside [0, maxval) the underlying data must be int32. The caller picks
// start/count so the byte range is valid under EITHER dtype.
__global__ void k_detect(const long long* __restrict__ p, long long start, int count,
                         long long maxval, int* flag) {
    __shared__ int bad;
    if (threadIdx.x == 0) bad = 0;
    __syncthreads();
    for (int i = threadIdx.x; i < count; i += blockDim.x) {
        long long v = p[start + i];
        if (v < 0 || v >= maxval) bad = 1;  // benign race
    }
    __syncthreads();
    if (threadIdx.x == 0) *flag = bad ? 0 : 1;
}

// ---------------- prep kernels ----------------
__global__ void k_deg_init(float* deg, int n) {
    int i = blockIdx.x * blockDim.x + threadIdx.x;
    if (i < n) deg[i] = 1.0f;  // self-loop
}

__global__ void k_zero(float* p, int n) {
    int i = blockIdx.x * blockDim.x + threadIdx.x;
    if (i < n) p[i] = 0.0f;
}

__global__ void k_prep_edges(const void* __restrict__ ei, int* __restrict__ src,
                             int* __restrict__ dst, float* deg, int E, int n,
                             const int* __restrict__ flag) {
    int i = blockIdx.x * blockDim.x + threadIdx.x;
    if (i >= E) return;
    int s, d;
    if (*flag) {
        const long long* p = (const long long*)ei;
        s = (int)p[i];
        d = (int)p[(size_t)E + i];
    } else {
        const int* p = (const int*)ei;
        s = p[i];
        d = p[(size_t)E + i];
    }
    if ((unsigned)s >= (unsigned)n) s = 0;  // defensive: never trap
    if ((unsigned)d >= (unsigned)n) d = 0;
    src[i] = s;
    dst[i] = d;
    atomicAdd(&deg[d], 1.0f);
}

__global__ void k_batch_cvt(const void* __restrict__ batch, int* __restrict__ b32,
                            int n, const int* __restrict__ flag) {
    int i = blockIdx.x * blockDim.x + threadIdx.x;
    if (i >= n) return;
    int b = (*flag) ? (int)((const long long*)batch)[i] : ((const int*)batch)[i];
    if ((unsigned)b >= (unsigned)NGRAPH) b = 0;
    b32[i] = b;
}

__global__ void k_dinv(const float* __restrict__ deg, float* __restrict__ dinv,
                       float* __restrict__ dinv2, int n) {
    int i = blockIdx.x * blockDim.x + threadIdx.x;
    if (i >= n) return;
    float r = rsqrtf(deg[i]);
    dinv[i] = r;
    dinv2[i] = r * r;
}

__global__ void k_norm(const int* __restrict__ src, const int* __restrict__ dst,
                       const float* __restrict__ dinv, float* __restrict__ norm, int E) {
    int i = blockIdx.x * blockDim.x + threadIdx.x;
    if (i >= E) return;
    norm[i] = dinv[src[i]] * dinv[dst[i]];
}

// y[n,f] = x[n,f] * dinv2[n]  (self-loop term; also zero-free init of agg buffer)
template <int F4>
__global__ void k_selfinit(const float* __restrict__ X, const float* __restrict__ dinv2,
                           float* __restrict__ Y, int n) {
    int i = blockIdx.x * blockDim.x + threadIdx.x;
    if (i >= n * F4) return;
    int node = i / F4;
    float s = dinv2[node];
    float4 v = ((const float4*)X)[i];
    v.x *= s; v.y *= s; v.z *= s; v.w *= s;
    ((float4*)Y)[i] = v;
}

// ---------------- edge scatter: Y[dst] += X[src] * norm  ----------------
// LOGS = log2(float4s per node row). 4 -> F=64, 3 -> F=32.
template <int LOGS>
__global__ void k_scatter(const float* __restrict__ X, float* __restrict__ Y,
                          const int* __restrict__ src, const int* __restrict__ dst,
                          const float* __restrict__ norm, int E) {
    const int S = 1 << LOGS;
    int t = blockIdx.x * blockDim.x + threadIdx.x;
    int e = t >> LOGS;
    int sub = t & (S - 1);
    if (e >= E) return;
    int s = src[e];
    int d = dst[e];
    float w = norm[e];
    float4 v = __ldg((const float4*)X + (size_t)s * S + sub);
    float* yp = Y + ((size_t)d * S + sub) * 4;
    atomicAdd(yp + 0, v.x * w);
    atomicAdd(yp + 1, v.y * w);
    atomicAdd(yp + 2, v.z * w);
    atomicAdd(yp + 3, v.w * w);
}

// ---------------- small GEMM: Y = act(X @ W) ----------------
template <int KIN, int KOUT, bool INACT, bool OUTACT>
__global__ void __launch_bounds__(256)
k_gemm(const float* __restrict__ X, const float* __restrict__ W,
       const float* __restrict__ bin, const float* __restrict__ bout,
       float* __restrict__ Y, int n) {
    __shared__ float Ws[KIN * KOUT];
    __shared__ float bins[KIN];
    __shared__ float bouts[KOUT];
    int tid = threadIdx.x;
    for (int i = tid; i < KIN * KOUT; i += 256) Ws[i] = W[i];
    if (INACT)  for (int i = tid; i < KIN;  i += 256) bins[i]  = bin[i];
    if (OUTACT) for (int i = tid; i < KOUT; i += 256) bouts[i] = bout[i];
    __syncthreads();

    int r0 = blockIdx.x * 512 + tid;
    int r1 = r0 + 256;
    if (r0 >= n) return;
    bool v1 = (r1 < n);
    const float4* x0 = (const float4*)(X + (size_t)r0 * KIN);
    const float4* x1 = v1 ? (const float4*)(X + (size_t)r1 * KIN) : x0;

    for (int jc = 0; jc < KOUT; jc += 16) {
        float acc0[16], acc1[16];
#pragma unroll
        for (int j = 0; j < 16; j++) { acc0[j] = 0.f; acc1[j] = 0.f; }
#pragma unroll 4
        for (int k4 = 0; k4 < KIN / 4; k4++) {
            float4 a = __ldg(&x0[k4]);
            float4 b = __ldg(&x1[k4]);
            if (INACT) {
                a.x = fmaxf(a.x + bins[k4 * 4 + 0], 0.f);
                a.y = fmaxf(a.y + bins[k4 * 4 + 1], 0.f);
                a.z = fmaxf(a.z + bins[k4 * 4 + 2], 0.f);
                a.w = fmaxf(a.w + bins[k4 * 4 + 3], 0.f);
                b.x = fmaxf(b.x + bins[k4 * 4 + 0], 0.f);
                b.y = fmaxf(b.y + bins[k4 * 4 + 1], 0.f);
                b.z = fmaxf(b.z + bins[k4 * 4 + 2], 0.f);
                b.w = fmaxf(b.w + bins[k4 * 4 + 3], 0.f);
            }
            float xa[4] = {a.x, a.y, a.z, a.w};
            float xb[4] = {b.x, b.y, b.z, b.w};
#pragma unroll
            for (int kk = 0; kk < 4; kk++) {
                const float4* wrow = (const float4*)&Ws[(k4 * 4 + kk) * KOUT + jc];
#pragma unroll
                for (int jj = 0; jj < 4; jj++) {
                    float4 w = wrow[jj];
                    acc0[jj * 4 + 0] += xa[kk] * w.x;
                    acc0[jj * 4 + 1] += xa[kk] * w.y;
                    acc0[jj * 4 + 2] += xa[kk] * w.z;
                    acc0[jj * 4 + 3] += xa[kk] * w.w;
                    acc1[jj * 4 + 0] += xb[kk] * w.x;
                    acc1[jj * 4 + 1] += xb[kk] * w.y;
                    acc1[jj * 4 + 2] += xb[kk] * w.z;
                    acc1[jj * 4 + 3] += xb[kk] * w.w;
                }
            }
        }
#pragma unroll
        for (int jj = 0; jj < 4; jj++) {
            float4 o0, o1;
            float* p0 = &acc0[jj * 4];
            float* p1 = &acc1[jj * 4];
            if (OUTACT) {
                o0.x = fmaxf(p0[0] + bouts[jc + jj * 4 + 0], 0.f);
                o0.y = fmaxf(p0[1] + bouts[jc + jj * 4 + 1], 0.f);
                o0.z = fmaxf(p0[2] + bouts[jc + jj * 4 + 2], 0.f);
                o0.w = fmaxf(p0[3] + bouts[jc + jj * 4 + 3], 0.f);
                o1.x = fmaxf(p1[0] + bouts[jc + jj * 4 + 0], 0.f);
                o1.y = fmaxf(p1[1] + bouts[jc + jj * 4 + 1], 0.f);
                o1.z = fmaxf(p1[2] + bouts[jc + jj * 4 + 2], 0.f);
                o1.w = fmaxf(p1[3] + bouts[jc + jj * 4 + 3], 0.f);
            } else {
                o0 = make_float4(p0[0], p0[1], p0[2], p0[3]);
                o1 = make_float4(p1[0], p1[1], p1[2], p1[3]);
            }
            ((float4*)(Y + (size_t)r0 * KOUT + jc))[jj] = o0;
            if (v1) ((float4*)(Y + (size_t)r1 * KOUT + jc))[jj] = o1;
        }
    }
}

// ---------------- pooling ----------------
__global__ void k_pool(const float* __restrict__ Y, const int* __restrict__ batch,
                       const float* __restrict__ b4, float* __restrict__ pool,
                       float* __restrict__ cnt, int n) {
    int gw = (blockIdx.x * blockDim.x + threadIdx.x) >> 5;
    int lane = threadIdx.x & 31;
    if (gw >= n) return;
    int b = batch[gw];
    float v = fmaxf(Y[(size_t)gw * 32 + lane] + b4[lane], 0.f);
    atomicAdd(&pool[b * 32 + lane], v);
    if (lane == 0) atomicAdd(&cnt[b], 1.0f);
}

__global__ void k_final(const float* __restrict__ pool, const float* __restrict__ cnt,
                        const float* __restrict__ Wfc, const float* __restrict__ bfc,
                        float* __restrict__ out) {
    int g = threadIdx.x;
    if (g >= NGRAPH) return;
    float s = 0.f;
#pragma unroll
    for (int f = 0; f < 32; f++) s += pool[g * 32 + f] * Wfc[f];
    out[g] = s / fmaxf(cnt[g], 1.0f) + bfc[0];
}

// ---------------- host ----------------
extern "C" void kernel_launch(void* const* d_in, const int* in_sizes, int n_in,
                              void* d_out, int out_size) {
    const float* x     = (const float*)d_in[0];
    const void*  ei    = d_in[1];
    const void*  batch = d_in[2];

    // Locate weight block by its unambiguous size signature.
    int base = -1;
    for (int i = 3; i + 9 < n_in; i++) {
        if (in_sizes[i] == 8192 && in_sizes[i + 1] == 128 &&
            in_sizes[i + 2] == 8192 && in_sizes[i + 3] == 64 &&
            in_sizes[i + 4] == 4096 && in_sizes[i + 5] == 64 &&
            in_sizes[i + 6] == 2048 && in_sizes[i + 7] == 32 &&
            in_sizes[i + 8] == 32 && in_sizes[i + 9] == 1) {
            base = i;
            break;
        }
    }
    if (base < 0) base = (n_in >= 14) ? 4 : 3;  // fallback

    const float* W1  = (const float*)d_in[base + 0];
    const float* b1  = (const float*)d_in[base + 1];
    const float* W2  = (const float*)d_in[base + 2];
    const float* b2  = (const float*)d_in[base + 3];
    const float* W3  = (const float*)d_in[base + 4];
    const float* b3  = (const float*)d_in[base + 5];
    const float* W4  = (const float*)d_in[base + 6];
    const float* b4  = (const float*)d_in[base + 7];
    const float* Wfc = (const float*)d_in[base + 8];
    const float* bfc = (const float*)d_in[base + 9];
    float* out = (float*)d_out;

    int n = in_sizes[0] / 64;
    int E = in_sizes[1] / 2;

    float *deg, *dinv, *dinv2, *normv, *h1, *t, *y, *pool, *cnt;
    int *src, *dst, *b32, *flag_ei, *flag_b;
    cudaGetSymbolAddress((void**)&deg,     g_deg);
    cudaGetSymbolAddress((void**)&dinv,    g_dinv);
    cudaGetSymbolAddress((void**)&dinv2,   g_dinv2);
    cudaGetSymbolAddress((void**)&src,     g_src);
    cudaGetSymbolAddress((void**)&dst,     g_dst);
    cudaGetSymbolAddress((void**)&b32,     g_b32);
    cudaGetSymbolAddress((void**)&normv,   g_norm);
    cudaGetSymbolAddress((void**)&h1,      g_h1);
    cudaGetSymbolAddress((void**)&t,       g_t);
    cudaGetSymbolAddress((void**)&y,       g_y);
    cudaGetSymbolAddress((void**)&pool,    g_pool);
    cudaGetSymbolAddress((void**)&cnt,     g_cnt);
    cudaGetSymbolAddress((void**)&flag_ei, g_flag_ei);
    cudaGetSymbolAddress((void**)&flag_b,  g_flag_b);

    const int TB = 256;
    auto cdiv = [](long long a, long long b) { return (int)((a + b - 1) / b); };

    // ---- dtype detection (windows valid under either int32 or int64) ----
    {
        int cnt_ei = (E / 2 < 4096) ? E / 2 : 4096;          // edge col 0 head
        k_detect<<<1, 256>>>((const long long*)ei, 0, cnt_ei, n, flag_ei);
        int cnt_b = (n / 2 < 4096) ? n / 2 : 4096;           // batch tail (sorted)
        long long start_b = (long long)(n / 2) - cnt_b;
        k_detect<<<1, 256>>>((const long long*)batch, start_b, cnt_b, NGRAPH, flag_b);
    }

    // ---- prep: degrees, norms, int32 indices ----
    k_deg_init<<<cdiv(n, TB), TB>>>(deg, n);
    k_prep_edges<<<cdiv(E, TB), TB>>>(ei, src, dst, deg, E, n, flag_ei);
    k_batch_cvt<<<cdiv(n, TB), TB>>>(batch, b32, n, flag_b);
    k_dinv<<<cdiv(n, TB), TB>>>(deg, dinv, dinv2, n);
    k_norm<<<cdiv(E, TB), TB>>>(src, dst, dinv, normv, E);

    // ---- layer 1: aggregate x (64), then GEMM 64->128 with bias+relu ----
    k_selfinit<16><<<cdiv((long long)n * 16, TB), TB>>>(x, dinv2, y, n);
    k_scatter<4><<<cdiv((long long)E * 16, TB), TB>>>(x, y, src, dst, normv, E);
    k_gemm<64, 128, false, true><<<cdiv(n, 512), 256>>>(y, W1, nullptr, b1, h1, n);

    // ---- layer 2: GEMM 128->64, then aggregate (64) ----
    k_gemm<128, 64, false, false><<<cdiv(n, 512), 256>>>(h1, W2, nullptr, nullptr, t, n);
    k_selfinit<16><<<cdiv((long long)n * 16, TB), TB>>>(t, dinv2, y, n);
    k_scatter<4><<<cdiv((long long)E * 16, TB), TB>>>(t, y, src, dst, normv, E);

    // ---- layer 3: relu(y+b2) @ W3 (64->64), aggregate (64) ----
    k_gemm<64, 64, true, false><<<cdiv(n, 512), 256>>>(y, W3, b2, nullptr, t, n);
    k_selfinit<16><<<cdiv((long long)n * 16, TB), TB>>>(t, dinv2, y, n);
    k_scatter<4><<<cdiv((long long)E * 16, TB), TB>>>(t, y, src, dst, normv, E);

    // ---- layer 4: relu(y+b3) @ W4 (64->32), aggregate (32) ----
    k_gemm<64, 32, true, false><<<cdiv(n, 512), 256>>>(y, W4, b3, nullptr, t, n);
    k_selfinit<8><<<cdiv((long long)n * 8, TB), TB>>>(t, dinv2, y, n);
    k_scatter<3><<<cdiv((long long)E * 8, TB), TB>>>(t, y, src, dst, normv, E);

    // ---- mean pool + FC ----
    k_zero<<<cdiv(NGRAPH * 32, TB), TB>>>(pool, NGRAPH * 32);
    k_zero<<<1, NGRAPH>>>(cnt, NGRAPH);
    k_pool<<<cdiv((long long)n * 32, TB), TB>>>(y, b32, b4, pool, cnt, n);
    k_final<<<1, 256>>>(pool, cnt, Wfc, bfc, out);
}

// round 6
// speedup vs baseline: 1.5315x; 1.5315x over previous
#include <cuda_runtime.h>

#define NMAX 100000
#define EMAX 1600000
#define NGRAPH 256

// ---------------- static scratch (no allocation allowed) ----------------
__device__ float g_deg[NMAX];
__device__ float g_dinv[NMAX];
__device__ float g_dinv2[NMAX];
__device__ int2  g_edge[EMAX];
__device__ int   g_b32[NMAX];
__device__ float g_h1[(size_t)NMAX * 128];
__device__ float g_t [(size_t)NMAX * 64];
__device__ float g_y [(size_t)NMAX * 64];
__device__ float g_pool[NGRAPH * 32];
__device__ float g_cnt[NGRAPH];
__device__ int   g_flag_ei;   // 1 = int64 data, 0 = int32 data
__device__ int   g_flag_b;

// ---------------- dtype detection (device-side, graph-safe) -------------
__global__ void k_detect(const long long* __restrict__ p, long long start, int count,
                         long long maxval, int* flag) {
    __shared__ int bad;
    if (threadIdx.x == 0) bad = 0;
    __syncthreads();
    for (int i = threadIdx.x; i < count; i += blockDim.x) {
        long long v = p[start + i];
        if (v < 0 || v >= maxval) bad = 1;  // benign race
    }
    __syncthreads();
    if (threadIdx.x == 0) *flag = bad ? 0 : 1;
}

// ---------------- prep kernels ----------------
__global__ void k_deg_init(float* deg, int n) {
    int i = blockIdx.x * blockDim.x + threadIdx.x;
    if (i < n) deg[i] = 1.0f;  // self-loop
}

__global__ void k_zero(float* p, int n) {
    int i = blockIdx.x * blockDim.x + threadIdx.x;
    if (i < n) p[i] = 0.0f;
}

__global__ void k_prep_edges(const void* __restrict__ ei, int2* __restrict__ edge,
                             float* deg, int E, int n, const int* __restrict__ flag) {
    int i = blockIdx.x * blockDim.x + threadIdx.x;
    if (i >= E) return;
    int s, d;
    if (*flag) {
        const long long* p = (const long long*)ei;
        s = (int)p[i];
        d = (int)p[(size_t)E + i];
    } else {
        const int* p = (const int*)ei;
        s = p[i];
        d = p[(size_t)E + i];
    }
    if ((unsigned)s >= (unsigned)n) s = 0;  // defensive: never trap
    if ((unsigned)d >= (unsigned)n) d = 0;
    edge[i] = make_int2(s, d);
    atomicAdd(&deg[d], 1.0f);
}

__global__ void k_batch_cvt(const void* __restrict__ batch, int* __restrict__ b32,
                            int n, const int* __restrict__ flag) {
    int i = blockIdx.x * blockDim.x + threadIdx.x;
    if (i >= n) return;
    int b = (*flag) ? (int)((const long long*)batch)[i] : ((const int*)batch)[i];
    if ((unsigned)b >= (unsigned)NGRAPH) b = 0;
    b32[i] = b;
}

__global__ void k_dinv(const float* __restrict__ deg, float* __restrict__ dinv,
                       float* __restrict__ dinv2, int n) {
    int i = blockIdx.x * blockDim.x + threadIdx.x;
    if (i >= n) return;
    float r = rsqrtf(deg[i]);
    dinv[i] = r;
    dinv2[i] = r * r;
}

// y[n,f] = x[n,f] * dinv2[n]  (self-loop term; also zero-free init of agg buffer)
template <int F4>
__global__ void k_selfinit(const float* __restrict__ X, const float* __restrict__ dinv2,
                           float* __restrict__ Y, int n) {
    int i = blockIdx.x * blockDim.x + threadIdx.x;
    if (i >= n * F4) return;
    int node = i / F4;
    float s = dinv2[node];
    float4 v = ((const float4*)X)[i];
    v.x *= s; v.y *= s; v.z *= s; v.w *= s;
    ((float4*)Y)[i] = v;
}

// ---------------- edge scatter: Y[dst] += X[src] * dinv[s]*dinv[d] ------
// LOGS = log2(float4s per node row). 4 -> F=64, 3 -> F=32.
// One RED.128 per thread: packed 16B sectors, 4x fewer RED issues than scalar.
template <int LOGS>
__global__ void k_scatter(const float* __restrict__ X, float* __restrict__ Y,
                          const int2* __restrict__ edge, const float* __restrict__ dinv,
                          int E) {
    const int S = 1 << LOGS;
    int t = blockIdx.x * blockDim.x + threadIdx.x;
    int e = t >> LOGS;
    int sub = t & (S - 1);
    if (e >= E) return;
    int2 ed = __ldg(&edge[e]);
    float w = __ldg(&dinv[ed.x]) * __ldg(&dinv[ed.y]);
    float4 v = __ldg((const float4*)X + (size_t)ed.x * S + sub);
    float4* yp = (float4*)Y + (size_t)ed.y * S + sub;
    asm volatile("red.global.add.v4.f32 [%0], {%1,%2,%3,%4};"
                 :: "l"(yp), "f"(v.x * w), "f"(v.y * w), "f"(v.z * w), "f"(v.w * w)
                 : "memory");
}

// ---------------- small GEMM: Y = act(X @ W) ----------------
template <int KIN, int KOUT, bool INACT, bool OUTACT>
__global__ void __launch_bounds__(256)
k_gemm(const float* __restrict__ X, const float* __restrict__ W,
       const float* __restrict__ bin, const float* __restrict__ bout,
       float* __restrict__ Y, int n) {
    __shared__ float Ws[KIN * KOUT];
    __shared__ float bins[KIN];
    __shared__ float bouts[KOUT];
    int tid = threadIdx.x;
    for (int i = tid; i < KIN * KOUT; i += 256) Ws[i] = W[i];
    if (INACT)  for (int i = tid; i < KIN;  i += 256) bins[i]  = bin[i];
    if (OUTACT) for (int i = tid; i < KOUT; i += 256) bouts[i] = bout[i];
    __syncthreads();

    int r0 = blockIdx.x * 512 + tid;
    int r1 = r0 + 256;
    if (r0 >= n) return;
    bool v1 = (r1 < n);
    const float4* x0 = (const float4*)(X + (size_t)r0 * KIN);
    const float4* x1 = v1 ? (const float4*)(X + (size_t)r1 * KIN) : x0;

    for (int jc = 0; jc < KOUT; jc += 16) {
        float acc0[16], acc1[16];
#pragma unroll
        for (int j = 0; j < 16; j++) { acc0[j] = 0.f; acc1[j] = 0.f; }
#pragma unroll 4
        for (int k4 = 0; k4 < KIN / 4; k4++) {
            float4 a = __ldg(&x0[k4]);
            float4 b = __ldg(&x1[k4]);
            if (INACT) {
                a.x = fmaxf(a.x + bins[k4 * 4 + 0], 0.f);
                a.y = fmaxf(a.y + bins[k4 * 4 + 1], 0.f);
                a.z = fmaxf(a.z + bins[k4 * 4 + 2], 0.f);
                a.w = fmaxf(a.w + bins[k4 * 4 + 3], 0.f);
                b.x = fmaxf(b.x + bins[k4 * 4 + 0], 0.f);
                b.y = fmaxf(b.y + bins[k4 * 4 + 1], 0.f);
                b.z = fmaxf(b.z + bins[k4 * 4 + 2], 0.f);
                b.w = fmaxf(b.w + bins[k4 * 4 + 3], 0.f);
            }
            float xa[4] = {a.x, a.y, a.z, a.w};
            float xb[4] = {b.x, b.y, b.z, b.w};
#pragma unroll
            for (int kk = 0; kk < 4; kk++) {
                const float4* wrow = (const float4*)&Ws[(k4 * 4 + kk) * KOUT + jc];
#pragma unroll
                for (int jj = 0; jj < 4; jj++) {
                    float4 w = wrow[jj];
                    acc0[jj * 4 + 0] += xa[kk] * w.x;
                    acc0[jj * 4 + 1] += xa[kk] * w.y;
                    acc0[jj * 4 + 2] += xa[kk] * w.z;
                    acc0[jj * 4 + 3] += xa[kk] * w.w;
                    acc1[jj * 4 + 0] += xb[kk] * w.x;
                    acc1[jj * 4 + 1] += xb[kk] * w.y;
                    acc1[jj * 4 + 2] += xb[kk] * w.z;
                    acc1[jj * 4 + 3] += xb[kk] * w.w;
                }
            }
        }
#pragma unroll
        for (int jj = 0; jj < 4; jj++) {
            float4 o0, o1;
            float* p0 = &acc0[jj * 4];
            float* p1 = &acc1[jj * 4];
            if (OUTACT) {
                o0.x = fmaxf(p0[0] + bouts[jc + jj * 4 + 0], 0.f);
                o0.y = fmaxf(p0[1] + bouts[jc + jj * 4 + 1], 0.f);
                o0.z = fmaxf(p0[2] + bouts[jc + jj * 4 + 2], 0.f);
                o0.w = fmaxf(p0[3] + bouts[jc + jj * 4 + 3], 0.f);
                o1.x = fmaxf(p1[0] + bouts[jc + jj * 4 + 0], 0.f);
                o1.y = fmaxf(p1[1] + bouts[jc + jj * 4 + 1], 0.f);
                o1.z = fmaxf(p1[2] + bouts[jc + jj * 4 + 2], 0.f);
                o1.w = fmaxf(p1[3] + bouts[jc + jj * 4 + 3], 0.f);
            } else {
                o0 = make_float4(p0[0], p0[1], p0[2], p0[3]);
                o1 = make_float4(p1[0], p1[1], p1[2], p1[3]);
            }
            ((float4*)(Y + (size_t)r0 * KOUT + jc))[jj] = o0;
            if (v1) ((float4*)(Y + (size_t)r1 * KOUT + jc))[jj] = o1;
        }
    }
}

// ---------------- pooling ----------------
__global__ void k_pool(const float* __restrict__ Y, const int* __restrict__ batch,
                       const float* __restrict__ b4, float* __restrict__ pool,
                       float* __restrict__ cnt, int n) {
    int gw = (blockIdx.x * blockDim.x + threadIdx.x) >> 5;
    int lane = threadIdx.x & 31;
    if (gw >= n) return;
    int b = batch[gw];
    float v = fmaxf(Y[(size_t)gw * 32 + lane] + b4[lane], 0.f);
    atomicAdd(&pool[b * 32 + lane], v);
    if (lane == 0) atomicAdd(&cnt[b], 1.0f);
}

__global__ void k_final(const float* __restrict__ pool, const float* __restrict__ cnt,
                        const float* __restrict__ Wfc, const float* __restrict__ bfc,
                        float* __restrict__ out) {
    int g = threadIdx.x;
    if (g >= NGRAPH) return;
    float s = 0.f;
#pragma unroll
    for (int f = 0; f < 32; f++) s += pool[g * 32 + f] * Wfc[f];
    out[g] = s / fmaxf(cnt[g], 1.0f) + bfc[0];
}

// ---------------- host ----------------
extern "C" void kernel_launch(void* const* d_in, const int* in_sizes, int n_in,
                              void* d_out, int out_size) {
    const float* x     = (const float*)d_in[0];
    const void*  ei    = d_in[1];
    const void*  batch = d_in[2];

    // Locate weight block by its unambiguous size signature.
    int base = -1;
    for (int i = 3; i + 9 < n_in; i++) {
        if (in_sizes[i] == 8192 && in_sizes[i + 1] == 128 &&
            in_sizes[i + 2] == 8192 && in_sizes[i + 3] == 64 &&
            in_sizes[i + 4] == 4096 && in_sizes[i + 5] == 64 &&
            in_sizes[i + 6] == 2048 && in_sizes[i + 7] == 32 &&
            in_sizes[i + 8] == 32 && in_sizes[i + 9] == 1) {
            base = i;
            break;
        }
    }
    if (base < 0) base = (n_in >= 14) ? 4 : 3;  // fallback

    const float* W1  = (const float*)d_in[base + 0];
    const float* b1  = (const float*)d_in[base + 1];
    const float* W2  = (const float*)d_in[base + 2];
    const float* b2  = (const float*)d_in[base + 3];
    const float* W3  = (const float*)d_in[base + 4];
    const float* b3  = (const float*)d_in[base + 5];
    const float* W4  = (const float*)d_in[base + 6];
    const float* b4  = (const float*)d_in[base + 7];
    const float* Wfc = (const float*)d_in[base + 8];
    const float* bfc = (const float*)d_in[base + 9];
    float* out = (float*)d_out;

    int n = in_sizes[0] / 64;
    int E = in_sizes[1] / 2;

    float *deg, *dinv, *dinv2, *h1, *t, *y, *pool, *cnt;
    int2* edge;
    int *b32, *flag_ei, *flag_b;
    cudaGetSymbolAddress((void**)&deg,     g_deg);
    cudaGetSymbolAddress((void**)&dinv,    g_dinv);
    cudaGetSymbolAddress((void**)&dinv2,   g_dinv2);
    cudaGetSymbolAddress((void**)&edge,    g_edge);
    cudaGetSymbolAddress((void**)&b32,     g_b32);
    cudaGetSymbolAddress((void**)&h1,      g_h1);
    cudaGetSymbolAddress((void**)&t,       g_t);
    cudaGetSymbolAddress((void**)&y,       g_y);
    cudaGetSymbolAddress((void**)&pool,    g_pool);
    cudaGetSymbolAddress((void**)&cnt,     g_cnt);
    cudaGetSymbolAddress((void**)&flag_ei, g_flag_ei);
    cudaGetSymbolAddress((void**)&flag_b,  g_flag_b);

    const int TB = 256;
    auto cdiv = [](long long a, long long b) { return (int)((a + b - 1) / b); };

    // Launch order puts the first F=64 scatter at slot 6 (ncu -s 5 -c 1 target).
    {
        int cnt_ei = (E / 2 < 4096) ? E / 2 : 4096;          // edge col 0 head
        k_detect<<<1, 256>>>((const long long*)ei, 0, cnt_ei, n, flag_ei);   // 1
    }
    k_deg_init<<<cdiv(n, TB), TB>>>(deg, n);                                 // 2
    k_prep_edges<<<cdiv(E, TB), TB>>>(ei, edge, deg, E, n, flag_ei);         // 3
    k_dinv<<<cdiv(n, TB), TB>>>(deg, dinv, dinv2, n);                        // 4

    // ---- layer 1: aggregate x (64), then GEMM 64->128 with bias+relu ----
    k_selfinit<16><<<cdiv((long long)n * 16, TB), TB>>>(x, dinv2, y, n);     // 5
    k_scatter<4><<<cdiv((long long)E * 16, TB), TB>>>(x, y, edge, dinv, E);  // 6 <- profiled
    k_gemm<64, 128, false, true><<<cdiv(n, 512), 256>>>(y, W1, nullptr, b1, h1, n);

    // ---- layer 2: GEMM 128->64, then aggregate (64) ----
    k_gemm<128, 64, false, false><<<cdiv(n, 512), 256>>>(h1, W2, nullptr, nullptr, t, n);
    k_selfinit<16><<<cdiv((long long)n * 16, TB), TB>>>(t, dinv2, y, n);
    k_scatter<4><<<cdiv((long long)E * 16, TB), TB>>>(t, y, edge, dinv, E);

    // ---- layer 3: relu(y+b2) @ W3 (64->64), aggregate (64) ----
    k_gemm<64, 64, true, false><<<cdiv(n, 512), 256>>>(y, W3, b2, nullptr, t, n);
    k_selfinit<16><<<cdiv((long long)n * 16, TB), TB>>>(t, dinv2, y, n);
    k_scatter<4><<<cdiv((long long)E * 16, TB), TB>>>(t, y, edge, dinv, E);

    // ---- layer 4: relu(y+b3) @ W4 (64->32), aggregate (32) ----
    k_gemm<64, 32, true, false><<<cdiv(n, 512), 256>>>(y, W4, b3, nullptr, t, n);
    k_selfinit<8><<<cdiv((long long)n * 8, TB), TB>>>(t, dinv2, y, n);
    k_scatter<3><<<cdiv((long long)E * 8, TB), TB>>>(t, y, edge, dinv, E);

    // ---- mean pool + FC ----
    {
        int cnt_b = (n / 2 < 4096) ? n / 2 : 4096;           // batch tail window
        long long start_b = (long long)(n / 2) - cnt_b;
        k_detect<<<1, 256>>>((const long long*)batch, start_b, cnt_b, NGRAPH, flag_b);
    }
    k_batch_cvt<<<cdiv(n, TB), TB>>>(batch, b32, n, flag_b);
    k_zero<<<cdiv(NGRAPH * 32, TB), TB>>>(pool, NGRAPH * 32);
    k_zero<<<1, NGRAPH>>>(cnt, NGRAPH);
    k_pool<<<cdiv((long long)n * 32, TB), TB>>>(y, b32, b4, pool, cnt, n);
    k_final<<<1, 256>>>(pool, cnt, Wfc, bfc, out);
}

// round 7
// speedup vs baseline: 1.9442x; 1.2695x over previous
#include <cuda_runtime.h>

#define NMAX 100000
#define EMAX 1600000
#define NGRAPH 256
#define SCAN_B 256

// ---------------- static scratch (no allocation allowed) ----------------
__device__ int    g_degi[NMAX];
__device__ float  g_dinv[NMAX];
__device__ float  g_dinv2[NMAX];
__device__ int2   g_edge[EMAX];
__device__ int    g_rowptr[NMAX + 1];
__device__ int    g_tmp[NMAX];
__device__ int    g_partial[(NMAX + SCAN_B - 1) / SCAN_B + 1];
__device__ int    g_fill[NMAX];
__device__ float2 g_adj[EMAX];     // .x = src index bits, .y = norm weight
__device__ int    g_b32[NMAX];
__device__ float  g_h1[(size_t)NMAX * 128];
__device__ float  g_t [(size_t)NMAX * 64];
__device__ float  g_y [(size_t)NMAX * 64];
__device__ float  g_pool[NGRAPH * 32];
__device__ float  g_cnt[NGRAPH];
__device__ int    g_flag_ei;   // 1 = int64 data, 0 = int32 data
__device__ int    g_flag_b;

// ---------------- dtype detection (device-side, graph-safe) -------------
__global__ void k_detect(const long long* __restrict__ p, long long start, int count,
                         long long maxval, int* flag) {
    __shared__ int bad;
    if (threadIdx.x == 0) bad = 0;
    __syncthreads();
    for (int i = threadIdx.x; i < count; i += blockDim.x) {
        long long v = p[start + i];
        if (v < 0 || v >= maxval) bad = 1;  // benign race
    }
    __syncthreads();
    if (threadIdx.x == 0) *flag = bad ? 0 : 1;
}

// ---------------- prep ----------------
__global__ void k_zero_int(int* p, int n) {
    int i = blockIdx.x * blockDim.x + threadIdx.x;
    if (i < n) p[i] = 0;
}
__global__ void k_zero(float* p, int n) {
    int i = blockIdx.x * blockDim.x + threadIdx.x;
    if (i < n) p[i] = 0.0f;
}

__global__ void k_prep_edges(const void* __restrict__ ei, int2* __restrict__ edge,
                             int* degi, int E, int n, const int* __restrict__ flag) {
    int i = blockIdx.x * blockDim.x + threadIdx.x;
    if (i >= E) return;
    int s, d;
    if (*flag) {
        const long long* p = (const long long*)ei;
        s = (int)p[i];
        d = (int)p[(size_t)E + i];
    } else {
        const int* p = (const int*)ei;
        s = p[i];
        d = p[(size_t)E + i];
    }
    if ((unsigned)s >= (unsigned)n) s = 0;  // defensive: never trap
    if ((unsigned)d >= (unsigned)n) d = 0;
    edge[i] = make_int2(s, d);
    atomicAdd(&degi[d], 1);
}

__global__ void k_batch_cvt(const void* __restrict__ batch, int* __restrict__ b32,
                            int n, const int* __restrict__ flag) {
    int i = blockIdx.x * blockDim.x + threadIdx.x;
    if (i >= n) return;
    int b = (*flag) ? (int)((const long long*)batch)[i] : ((const int*)batch)[i];
    if ((unsigned)b >= (unsigned)NGRAPH) b = 0;
    b32[i] = b;
}

__global__ void k_dinv(const int* __restrict__ degi, float* __restrict__ dinv,
                       float* __restrict__ dinv2, int n) {
    int i = blockIdx.x * blockDim.x + threadIdx.x;
    if (i >= n) return;
    float r = rsqrtf(1.0f + (float)degi[i]);
    dinv[i] = r;
    dinv2[i] = r * r;
}

// ---------------- prefix sum (exclusive) over degi -> rowptr ------------
__global__ void k_scan1(const int* __restrict__ degi, int* __restrict__ tmp,
                        int* __restrict__ partial, int n) {
    __shared__ int sh[SCAN_B];
    int t = threadIdx.x;
    int i = blockIdx.x * SCAN_B + t;
    int val = (i < n) ? degi[i] : 0;
    sh[t] = val;
    __syncthreads();
    for (int off = 1; off < SCAN_B; off <<= 1) {
        int x = (t >= off) ? sh[t - off] : 0;
        __syncthreads();
        sh[t] += x;
        __syncthreads();
    }
    if (i < n) tmp[i] = sh[t] - val;              // exclusive within block
    if (t == SCAN_B - 1) partial[blockIdx.x] = sh[t];
}

__global__ void k_scan_part(int* partial, int nb) {
    __shared__ int sh[512];
    __shared__ int carry;
    int t = threadIdx.x;
    if (t == 0) carry = 0;
    __syncthreads();
    for (int base = 0; base < nb; base += 512) {
        int idx = base + t;
        int val = (idx < nb) ? partial[idx] : 0;
        sh[t] = val;
        __syncthreads();
        for (int off = 1; off < 512; off <<= 1) {
            int x = (t >= off) ? sh[t - off] : 0;
            __syncthreads();
            sh[t] += x;
            __syncthreads();
        }
        if (idx < nb) partial[idx] = sh[t] - val + carry;
        __syncthreads();
        if (t == 0) carry += sh[511];
        __syncthreads();
    }
}

__global__ void k_scan_add(const int* __restrict__ tmp, const int* __restrict__ partial,
                           int* __restrict__ rowptr, int n, int E) {
    int i = blockIdx.x * blockDim.x + threadIdx.x;
    if (i < n) rowptr[i] = tmp[i] + partial[i / SCAN_B];
    if (i == 0) rowptr[n] = E;
}

__global__ void k_fill(const int2* __restrict__ edge, const int* __restrict__ rowptr,
                       int* __restrict__ fill, const float* __restrict__ dinv,
                       float2* __restrict__ adj, int E) {
    int i = blockIdx.x * blockDim.x + threadIdx.x;
    if (i >= E) return;
    int2 ed = edge[i];
    int pos = rowptr[ed.y] + atomicAdd(&fill[ed.y], 1);
    adj[pos] = make_float2(__int_as_float(ed.x), dinv[ed.x] * dinv[ed.y]);
}

// ---------------- CSR gather: Y[d] = sum_e w*X[src] + dinv2[d]*X[d] -----
// One warp per dst node. F=64: lane owns a float2 column pair.
__global__ void __launch_bounds__(256)
k_gather64(const float* __restrict__ X, float* __restrict__ Y,
           const int* __restrict__ rowptr, const float2* __restrict__ adj,
           const float* __restrict__ dinv2, int n) {
    int warp = (blockIdx.x * 256 + threadIdx.x) >> 5;
    int lane = threadIdx.x & 31;
    if (warp >= n) return;
    int start = __ldg(&rowptr[warp]);
    int end   = __ldg(&rowptr[warp + 1]);
    const float2* Xp = (const float2*)X;
    float sw = __ldg(&dinv2[warp]);
    float2 a = __ldg(Xp + (size_t)warp * 32 + lane);
    float2 acc = make_float2(a.x * sw, a.y * sw);
    int i = start;
    for (; i + 1 < end; i += 2) {
        float2 e0 = __ldg(&adj[i]);
        float2 e1 = __ldg(&adj[i + 1]);
        int s0 = __float_as_int(e0.x);
        int s1 = __float_as_int(e1.x);
        float2 v0 = __ldg(Xp + (size_t)s0 * 32 + lane);
        float2 v1 = __ldg(Xp + (size_t)s1 * 32 + lane);
        acc.x += v0.x * e0.y; acc.y += v0.y * e0.y;
        acc.x += v1.x * e1.y; acc.y += v1.y * e1.y;
    }
    if (i < end) {
        float2 e0 = __ldg(&adj[i]);
        int s0 = __float_as_int(e0.x);
        float2 v0 = __ldg(Xp + (size_t)s0 * 32 + lane);
        acc.x += v0.x * e0.y; acc.y += v0.y * e0.y;
    }
    ((float2*)Y)[(size_t)warp * 32 + lane] = acc;
}

// F=32: lane owns one float.
__global__ void __launch_bounds__(256)
k_gather32(const float* __restrict__ X, float* __restrict__ Y,
           const int* __restrict__ rowptr, const float2* __restrict__ adj,
           const float* __restrict__ dinv2, int n) {
    int warp = (blockIdx.x * 256 + threadIdx.x) >> 5;
    int lane = threadIdx.x & 31;
    if (warp >= n) return;
    int start = __ldg(&rowptr[warp]);
    int end   = __ldg(&rowptr[warp + 1]);
    float acc = __ldg(X + (size_t)warp * 32 + lane) * __ldg(&dinv2[warp]);
    int i = start;
    for (; i + 1 < end; i += 2) {
        float2 e0 = __ldg(&adj[i]);
        float2 e1 = __ldg(&adj[i + 1]);
        float v0 = __ldg(X + (size_t)__float_as_int(e0.x) * 32 + lane);
        float v1 = __ldg(X + (size_t)__float_as_int(e1.x) * 32 + lane);
        acc += v0 * e0.y + v1 * e1.y;
    }
    if (i < end) {
        float2 e0 = __ldg(&adj[i]);
        acc += __ldg(X + (size_t)__float_as_int(e0.x) * 32 + lane) * e0.y;
    }
    Y[(size_t)warp * 32 + lane] = acc;
}

// ---------------- small GEMM: Y = act(X @ W) ----------------
template <int KIN, int KOUT, bool INACT, bool OUTACT>
__global__ void __launch_bounds__(256)
k_gemm(const float* __restrict__ X, const float* __restrict__ W,
       const float* __restrict__ bin, const float* __restrict__ bout,
       float* __restrict__ Y, int n) {
    __shared__ float Ws[KIN * KOUT];
    __shared__ float bins[KIN];
    __shared__ float bouts[KOUT];
    int tid = threadIdx.x;
    for (int i = tid; i < KIN * KOUT; i += 256) Ws[i] = W[i];
    if (INACT)  for (int i = tid; i < KIN;  i += 256) bins[i]  = bin[i];
    if (OUTACT) for (int i = tid; i < KOUT; i += 256) bouts[i] = bout[i];
    __syncthreads();

    int r0 = blockIdx.x * 512 + tid;
    int r1 = r0 + 256;
    if (r0 >= n) return;
    bool v1 = (r1 < n);
    const float4* x0 = (const float4*)(X + (size_t)r0 * KIN);
    const float4* x1 = v1 ? (const float4*)(X + (size_t)r1 * KIN) : x0;

    for (int jc = 0; jc < KOUT; jc += 16) {
        float acc0[16], acc1[16];
#pragma unroll
        for (int j = 0; j < 16; j++) { acc0[j] = 0.f; acc1[j] = 0.f; }
#pragma unroll 4
        for (int k4 = 0; k4 < KIN / 4; k4++) {
            float4 a = __ldg(&x0[k4]);
            float4 b = __ldg(&x1[k4]);
            if (INACT) {
                a.x = fmaxf(a.x + bins[k4 * 4 + 0], 0.f);
                a.y = fmaxf(a.y + bins[k4 * 4 + 1], 0.f);
                a.z = fmaxf(a.z + bins[k4 * 4 + 2], 0.f);
                a.w = fmaxf(a.w + bins[k4 * 4 + 3], 0.f);
                b.x = fmaxf(b.x + bins[k4 * 4 + 0], 0.f);
                b.y = fmaxf(b.y + bins[k4 * 4 + 1], 0.f);
                b.z = fmaxf(b.z + bins[k4 * 4 + 2], 0.f);
                b.w = fmaxf(b.w + bins[k4 * 4 + 3], 0.f);
            }
            float xa[4] = {a.x, a.y, a.z, a.w};
            float xb[4] = {b.x, b.y, b.z, b.w};
#pragma unroll
            for (int kk = 0; kk < 4; kk++) {
                const float4* wrow = (const float4*)&Ws[(k4 * 4 + kk) * KOUT + jc];
#pragma unroll
                for (int jj = 0; jj < 4; jj++) {
                    float4 w = wrow[jj];
                    acc0[jj * 4 + 0] += xa[kk] * w.x;
                    acc0[jj * 4 + 1] += xa[kk] * w.y;
                    acc0[jj * 4 + 2] += xa[kk] * w.z;
                    acc0[jj * 4 + 3] += xa[kk] * w.w;
                    acc1[jj * 4 + 0] += xb[kk] * w.x;
                    acc1[jj * 4 + 1] += xb[kk] * w.y;
                    acc1[jj * 4 + 2] += xb[kk] * w.z;
                    acc1[jj * 4 + 3] += xb[kk] * w.w;
                }
            }
        }
#pragma unroll
        for (int jj = 0; jj < 4; jj++) {
            float4 o0, o1;
            float* p0 = &acc0[jj * 4];
            float* p1 = &acc1[jj * 4];
            if (OUTACT) {
                o0.x = fmaxf(p0[0] + bouts[jc + jj * 4 + 0], 0.f);
                o0.y = fmaxf(p0[1] + bouts[jc + jj * 4 + 1], 0.f);
                o0.z = fmaxf(p0[2] + bouts[jc + jj * 4 + 2], 0.f);
                o0.w = fmaxf(p0[3] + bouts[jc + jj * 4 + 3], 0.f);
                o1.x = fmaxf(p1[0] + bouts[jc + jj * 4 + 0], 0.f);
                o1.y = fmaxf(p1[1] + bouts[jc + jj * 4 + 1], 0.f);
                o1.z = fmaxf(p1[2] + bouts[jc + jj * 4 + 2], 0.f);
                o1.w = fmaxf(p1[3] + bouts[jc + jj * 4 + 3], 0.f);
            } else {
                o0 = make_float4(p0[0], p0[1], p0[2], p0[3]);
                o1 = make_float4(p1[0], p1[1], p1[2], p1[3]);
            }
            ((float4*)(Y + (size_t)r0 * KOUT + jc))[jj] = o0;
            if (v1) ((float4*)(Y + (size_t)r1 * KOUT + jc))[jj] = o1;
        }
    }
}

// ---------------- pooling ----------------
__global__ void k_pool(const float* __restrict__ Y, const int* __restrict__ batch,
                       const float* __restrict__ b4, float* __restrict__ pool,
                       float* __restrict__ cnt, int n) {
    int gw = (blockIdx.x * blockDim.x + threadIdx.x) >> 5;
    int lane = threadIdx.x & 31;
    if (gw >= n) return;
    int b = batch[gw];
    float v = fmaxf(Y[(size_t)gw * 32 + lane] + b4[lane], 0.f);
    atomicAdd(&pool[b * 32 + lane], v);
    if (lane == 0) atomicAdd(&cnt[b], 1.0f);
}

__global__ void k_final(const float* __restrict__ pool, const float* __restrict__ cnt,
                        const float* __restrict__ Wfc, const float* __restrict__ bfc,
                        float* __restrict__ out) {
    int g = threadIdx.x;
    if (g >= NGRAPH) return;
    float s = 0.f;
#pragma unroll
    for (int f = 0; f < 32; f++) s += pool[g * 32 + f] * Wfc[f];
    out[g] = s / fmaxf(cnt[g], 1.0f) + bfc[0];
}

// ---------------- host ----------------
extern "C" void kernel_launch(void* const* d_in, const int* in_sizes, int n_in,
                              void* d_out, int out_size) {
    const float* x     = (const float*)d_in[0];
    const void*  ei    = d_in[1];
    const void*  batch = d_in[2];

    // Locate weight block by its unambiguous size signature.
    int base = -1;
    for (int i = 3; i + 9 < n_in; i++) {
        if (in_sizes[i] == 8192 && in_sizes[i + 1] == 128 &&
            in_sizes[i + 2] == 8192 && in_sizes[i + 3] == 64 &&
            in_sizes[i + 4] == 4096 && in_sizes[i + 5] == 64 &&
            in_sizes[i + 6] == 2048 && in_sizes[i + 7] == 32 &&
            in_sizes[i + 8] == 32 && in_sizes[i + 9] == 1) {
            base = i;
            break;
        }
    }
    if (base < 0) base = (n_in >= 14) ? 4 : 3;  // fallback

    const float* W1  = (const float*)d_in[base + 0];
    const float* b1  = (const float*)d_in[base + 1];
    const float* W2  = (const float*)d_in[base + 2];
    const float* b2  = (const float*)d_in[base + 3];
    const float* W3  = (const float*)d_in[base + 4];
    const float* b3  = (const float*)d_in[base + 5];
    const float* W4  = (const float*)d_in[base + 6];
    const float* b4  = (const float*)d_in[base + 7];
    const float* Wfc = (const float*)d_in[base + 8];
    const float* bfc = (const float*)d_in[base + 9];
    float* out = (float*)d_out;

    int n = in_sizes[0] / 64;
    int E = in_sizes[1] / 2;

    float *dinv, *dinv2, *h1, *t, *y, *pool, *cnt;
    float2* adj;
    int2* edge;
    int *degi, *rowptr, *tmp, *partial, *fill, *b32, *flag_ei, *flag_b;
    cudaGetSymbolAddress((void**)&degi,    g_degi);
    cudaGetSymbolAddress((void**)&dinv,    g_dinv);
    cudaGetSymbolAddress((void**)&dinv2,   g_dinv2);
    cudaGetSymbolAddress((void**)&edge,    g_edge);
    cudaGetSymbolAddress((void**)&rowptr,  g_rowptr);
    cudaGetSymbolAddress((void**)&tmp,     g_tmp);
    cudaGetSymbolAddress((void**)&partial, g_partial);
    cudaGetSymbolAddress((void**)&fill,    g_fill);
    cudaGetSymbolAddress((void**)&adj,     g_adj);
    cudaGetSymbolAddress((void**)&b32,     g_b32);
    cudaGetSymbolAddress((void**)&h1,      g_h1);
    cudaGetSymbolAddress((void**)&t,       g_t);
    cudaGetSymbolAddress((void**)&y,       g_y);
    cudaGetSymbolAddress((void**)&pool,    g_pool);
    cudaGetSymbolAddress((void**)&cnt,     g_cnt);
    cudaGetSymbolAddress((void**)&flag_ei, g_flag_ei);
    cudaGetSymbolAddress((void**)&flag_b,  g_flag_b);

    const int TB = 256;
    auto cdiv = [](long long a, long long b) { return (int)((a + b - 1) / b); };
    int nb = cdiv(n, SCAN_B);

    // ---- dtype detection ----
    {
        int cnt_ei = (E / 2 < 4096) ? E / 2 : 4096;
        k_detect<<<1, 256>>>((const long long*)ei, 0, cnt_ei, n, flag_ei);
        int cnt_b = (n / 2 < 4096) ? n / 2 : 4096;
        long long start_b = (long long)(n / 2) - cnt_b;
        k_detect<<<1, 256>>>((const long long*)batch, start_b, cnt_b, NGRAPH, flag_b);
    }

    // ---- CSR build ----
    k_zero_int<<<cdiv(n, TB), TB>>>(degi, n);
    k_prep_edges<<<cdiv(E, TB), TB>>>(ei, edge, degi, E, n, flag_ei);
    k_dinv<<<cdiv(n, TB), TB>>>(degi, dinv, dinv2, n);
    k_scan1<<<nb, SCAN_B>>>(degi, tmp, partial, n);
    k_scan_part<<<1, 512>>>(partial, nb);
    k_scan_add<<<cdiv(n, TB), TB>>>(tmp, partial, rowptr, n, E);
    k_zero_int<<<cdiv(n, TB), TB>>>(fill, n);
    k_fill<<<cdiv(E, TB), TB>>>(edge, rowptr, fill, dinv, adj, E);

    int gblocks = cdiv((long long)n * 32, TB);  // one warp per node

    // ---- layer 1: aggregate x (64), then GEMM 64->128 with bias+relu ----
    k_gather64<<<gblocks, TB>>>(x, y, rowptr, adj, dinv2, n);
    k_gemm<64, 128, false, true><<<cdiv(n, 512), 256>>>(y, W1, nullptr, b1, h1, n);

    // ---- layer 2: GEMM 128->64, then aggregate (64) ----
    k_gemm<128, 64, false, false><<<cdiv(n, 512), 256>>>(h1, W2, nullptr, nullptr, t, n);
    k_gather64<<<gblocks, TB>>>(t, y, rowptr, adj, dinv2, n);

    // ---- layer 3: relu(y+b2) @ W3 (64->64), aggregate (64) ----
    k_gemm<64, 64, true, false><<<cdiv(n, 512), 256>>>(y, W3, b2, nullptr, t, n);
    k_gather64<<<gblocks, TB>>>(t, y, rowptr, adj, dinv2, n);

    // ---- layer 4: relu(y+b3) @ W4 (64->32), aggregate (32) ----
    k_gemm<64, 32, true, false><<<cdiv(n, 512), 256>>>(y, W4, b3, nullptr, t, n);
    k_gather32<<<gblocks, TB>>>(t, y, rowptr, adj, dinv2, n);

    // ---- mean pool + FC ----
    k_batch_cvt<<<cdiv(n, TB), TB>>>(batch, b32, n, flag_b);
    k_zero<<<cdiv(NGRAPH * 32, TB), TB>>>(pool, NGRAPH * 32);
    k_zero<<<1, NGRAPH>>>(cnt, NGRAPH);
    k_pool<<<cdiv((long long)n * 32, TB), TB>>>(y, b32, b4, pool, cnt, n);
    k_final<<<1, 256>>>(pool, cnt, Wfc, bfc, out);
}